// round 15
// baseline (speedup 1.0000x reference)
#include <cuda_runtime.h>
#include <cstdint>

namespace {

constexpr int CDIM = 256;
constexpr int FDIM = 512;
constexpr int NDIM = 1024;
constexpr int TW = 128;            // tile width (positions)
constexpr int NTILES = NDIM / TW;  // 8
constexpr int NTHREADS = 512;
constexpr int NW = 16;
constexpr int CS = 4 * NDIM;       // channel stride in x (floats)
constexpr int YST = 136;           // yt/hbuf row stride
constexpr int WST = 264;           // big panel row stride [k][256]
constexpr int WSTS = 72;           // small panel row stride [k][64]
constexpr int PLANE = 8 * WST;     // one k-panel plane (2112 floats)
constexpr int PBUF = 2 * PLANE;    // hi + lo
constexpr float EPS = 1e-5f;
constexpr unsigned TMASK = 0xFFFFE000u;  // tf32 truncation mask

struct Smem {
  float yt[CDIM * YST];     // y1/attn/y2 tile
  float hbuf[64 * YST];     // FFN H block; aliases qA + LN2 red
  float wp[2 * PBUF];       // dbuf x (hi,lo) weight panels
  float meanA[NDIM];
  float rstdA[NDIM];
  float g1[CDIM], be1[CDIM], g2v[CDIM], be2[CDIM], avec[CDIM];
  float ctxv[CDIM], ybar[CDIM], bvv[CDIM], bov[CDIM], bf2v[CDIM];
  float bf1v[FDIM];
  float m2s[TW], r2s[TW];
  float scratch[40];
};

__device__ __forceinline__ void mma8(float* d, const unsigned* a,
                                     unsigned b0, unsigned b1) {
  asm volatile(
      "mma.sync.aligned.m16n8k8.row.col.f32.tf32.tf32.f32 "
      "{%0,%1,%2,%3}, {%4,%5,%6,%7}, {%8,%9}, {%0,%1,%2,%3};\n"
      : "+f"(d[0]), "+f"(d[1]), "+f"(d[2]), "+f"(d[3])
      : "r"(a[0]), "r"(a[1]), "r"(a[2]), "r"(a[3]), "r"(b0), "r"(b1));
}

__device__ __forceinline__ float warpSum(float v) {
#pragma unroll
  for (int o = 16; o; o >>= 1) v += __shfl_xor_sync(0xffffffffu, v, o);
  return v;
}

__device__ __forceinline__ float blockSum(float v, float* scr) {
  v = warpSum(v);
  const int w = threadIdx.x >> 5;
  if ((threadIdx.x & 31) == 0) scr[w] = v;
  __syncthreads();
  if (threadIdx.x == 0) {
    float t = 0.f;
#pragma unroll
    for (int i = 0; i < NW; i++) t += scr[i];
    scr[20] = t;
  }
  __syncthreads();
  float r = scr[20];
  __syncthreads();
  return r;
}

__device__ __forceinline__ float blockMax(float v, float* scr) {
#pragma unroll
  for (int o = 16; o; o >>= 1) v = fmaxf(v, __shfl_xor_sync(0xffffffffu, v, o));
  const int w = threadIdx.x >> 5;
  if ((threadIdx.x & 31) == 0) scr[w] = v;
  __syncthreads();
  if (threadIdx.x == 0) {
    float t = scr[0];
#pragma unroll
    for (int i = 1; i < NW; i++) t = fmaxf(t, scr[i]);
    scr[20] = t;
  }
  __syncthreads();
  float r = scr[20];
  __syncthreads();
  return r;
}

// Split 4 weight values into tf32-hi + tf32-lo planes at rows kh..kh+4.
__device__ __forceinline__ void storeSplit4(float* wh, float* wl, int lrow,
                                            int kh, const float4& f) {
#pragma unroll
  for (int i = 0; i < 4; i++) {
    float v = (&f.x)[i];
    unsigned h = __float_as_uint(v) & TMASK;
    wh[(kh + i) * WST + lrow] = __uint_as_float(h);
    float lo = v - __uint_as_float(h);
    wl[(kh + i) * WST + lrow] = __uint_as_float(__float_as_uint(lo) & TMASK);
  }
}

// Big GEMM: acc[256 x TW] += W[256 x kdim](row-major ld=ldw, cols kcol0..) @ Ys
// 16 warps, 2-D warp tile: warp w covers rows (w&7)*32 (2 m-frags) x cols
// (w>>3)*64 (8 n-frags). TF32 3-pass split. Panel PD=8, double-buffered.
__device__ __forceinline__ void gemmBig(const float* __restrict__ Wg, int ldw,
                                        int kcol0, int kdim,
                                        const float* __restrict__ Ys,
                                        float (&acc)[2][8][4], float* wp,
                                        int tid, int wrow, int cbase,
                                        int gid, int tig) {
  const int lrow = tid & 255;
  const int kh = (tid >> 8) * 4;
  const float* gp = Wg + (size_t)lrow * ldw + kcol0 + kh;
  float4 f = *(const float4*)gp;
  storeSplit4(wp, wp + PLANE, lrow, kh, f);
  __syncthreads();
  const int P = kdim / 8;
#pragma unroll 1
  for (int p = 0; p < P; p++) {
    if (p + 1 < P) f = *(const float4*)(gp + (p + 1) * 8);
    const float* wh = wp + (p & 1) * PBUF;
    const float* wl = wh + PLANE;
    unsigned ah[2][4], al[2][4];
#pragma unroll
    for (int mi = 0; mi < 2; mi++) {
      const int rb = wrow + mi * 16 + gid;
      ah[mi][0] = __float_as_uint(wh[tig * WST + rb]);
      ah[mi][1] = __float_as_uint(wh[tig * WST + rb + 8]);
      ah[mi][2] = __float_as_uint(wh[(tig + 4) * WST + rb]);
      ah[mi][3] = __float_as_uint(wh[(tig + 4) * WST + rb + 8]);
      al[mi][0] = __float_as_uint(wl[tig * WST + rb]);
      al[mi][1] = __float_as_uint(wl[tig * WST + rb + 8]);
      al[mi][2] = __float_as_uint(wl[(tig + 4) * WST + rb]);
      al[mi][3] = __float_as_uint(wl[(tig + 4) * WST + rb + 8]);
    }
    const float* yb = Ys + p * 8 * YST;
#pragma unroll
    for (int nf = 0; nf < 8; nf++) {
      const int cb = cbase + nf * 8 + gid;
      float y0 = yb[tig * YST + cb];
      float y1 = yb[(tig + 4) * YST + cb];
      unsigned bh0 = __float_as_uint(y0) & TMASK;
      unsigned bh1 = __float_as_uint(y1) & TMASK;
      unsigned bl0 = __float_as_uint(y0 - __uint_as_float(bh0)) & TMASK;
      unsigned bl1 = __float_as_uint(y1 - __uint_as_float(bh1)) & TMASK;
      mma8(acc[0][nf], ah[0], bh0, bh1);
      mma8(acc[0][nf], ah[0], bl0, bl1);
      mma8(acc[0][nf], al[0], bh0, bh1);
      mma8(acc[1][nf], ah[1], bh0, bh1);
      mma8(acc[1][nf], ah[1], bl0, bl1);
      mma8(acc[1][nf], al[1], bh0, bh1);
    }
    if (p + 1 < P) {
      float* wh2 = wp + ((p + 1) & 1) * PBUF;
      storeSplit4(wh2, wh2 + PLANE, lrow, kh, f);
    }
    __syncthreads();
  }
}

// Small GEMM (ffn1 block): acc2[64 x TW] += W[64 x 256] @ Ys.
// Warp w: m-frag (w&3)*16, col-quarter (w>>2)*32 (4 n-frags).
// Panel PD=16 ([k][64], stride 72), double-buffered; same 3-pass split.
__device__ __forceinline__ void gemmSmall(const float* __restrict__ Wg,
                                          const float* __restrict__ Ys,
                                          float (&acc2)[4][4], float* wp,
                                          int tid, int wid, int gid, int tig) {
  const int mr = (wid & 3) * 16;
  const int cbase = (wid >> 2) * 32;
  const int lrow = tid & 63;
  const int ks = (tid >> 6) * 2;   // 0,2,..,14
  const float* gp = Wg + (size_t)lrow * CDIM + ks;
  float2 f = *(const float2*)gp;
  {
    float* wh = wp;
    float* wl = wp + PLANE;
#pragma unroll
    for (int i = 0; i < 2; i++) {
      float v = (&f.x)[i];
      unsigned h = __float_as_uint(v) & TMASK;
      wh[(ks + i) * WSTS + lrow] = __uint_as_float(h);
      float lo = v - __uint_as_float(h);
      wl[(ks + i) * WSTS + lrow] = __uint_as_float(__float_as_uint(lo) & TMASK);
    }
  }
  __syncthreads();
  const int P = CDIM / 16;
#pragma unroll 1
  for (int p = 0; p < P; p++) {
    if (p + 1 < P) f = *(const float2*)(gp + (p + 1) * 16);
    const float* wh = wp + (p & 1) * PBUF;
    const float* wl = wh + PLANE;
#pragma unroll
    for (int kc = 0; kc < 16; kc += 8) {
      unsigned ah[4], al[4];
      const int rb = mr + gid;
      ah[0] = __float_as_uint(wh[(kc + tig) * WSTS + rb]);
      ah[1] = __float_as_uint(wh[(kc + tig) * WSTS + rb + 8]);
      ah[2] = __float_as_uint(wh[(kc + tig + 4) * WSTS + rb]);
      ah[3] = __float_as_uint(wh[(kc + tig + 4) * WSTS + rb + 8]);
      al[0] = __float_as_uint(wl[(kc + tig) * WSTS + rb]);
      al[1] = __float_as_uint(wl[(kc + tig) * WSTS + rb + 8]);
      al[2] = __float_as_uint(wl[(kc + tig + 4) * WSTS + rb]);
      al[3] = __float_as_uint(wl[(kc + tig + 4) * WSTS + rb + 8]);
      const float* yb = Ys + (p * 16 + kc) * YST;
#pragma unroll
      for (int nf = 0; nf < 4; nf++) {
        const int cb = cbase + nf * 8 + gid;
        float y0 = yb[tig * YST + cb];
        float y1 = yb[(tig + 4) * YST + cb];
        unsigned bh0 = __float_as_uint(y0) & TMASK;
        unsigned bh1 = __float_as_uint(y1) & TMASK;
        unsigned bl0 = __float_as_uint(y0 - __uint_as_float(bh0)) & TMASK;
        unsigned bl1 = __float_as_uint(y1 - __uint_as_float(bh1)) & TMASK;
        mma8(acc2[nf], ah, bh0, bh1);
        mma8(acc2[nf], ah, bl0, bl1);
        mma8(acc2[nf], al, bh0, bh1);
      }
    }
    if (p + 1 < P) {
      float* wh2 = wp + ((p + 1) & 1) * PBUF;
      float* wl2 = wh2 + PLANE;
#pragma unroll
      for (int i = 0; i < 2; i++) {
        float v = (&f.x)[i];
        unsigned h = __float_as_uint(v) & TMASK;
        wh2[(ks + i) * WSTS + lrow] = __uint_as_float(h);
        float lo = v - __uint_as_float(h);
        wl2[(ks + i) * WSTS + lrow] = __uint_as_float(__float_as_uint(lo) & TMASK);
      }
    }
    __syncthreads();
  }
}

__global__ void __launch_bounds__(NTHREADS, 1)
fused_block_kernel(const float* __restrict__ x,
                   const float* __restrict__ ln1_w, const float* __restrict__ ln1_b,
                   const float* __restrict__ qkv_w, const float* __restrict__ qkv_b,
                   const float* __restrict__ out_w, const float* __restrict__ out_b,
                   const float* __restrict__ ln2_w, const float* __restrict__ ln2_b,
                   const float* __restrict__ ffn1_w, const float* __restrict__ ffn1_b,
                   const float* __restrict__ ffn2_w, const float* __restrict__ ffn2_b,
                   float* __restrict__ out) {
  extern __shared__ __align__(16) char smem_raw[];
  Smem* s = reinterpret_cast<Smem*>(smem_raw);
  const int tid = threadIdx.x;
  const int b = blockIdx.x >> 2;
  const int p = blockIdx.x & 3;
  const size_t base = (size_t)b * (CDIM * 4 * NDIM) + (size_t)p * NDIM;
  float* qA = s->hbuf;  // alias: q / u values live only in phases 1-2

  // ---------- Phase 0 ----------
  for (int i = tid; i < CDIM; i += NTHREADS) {
    float g = ln1_w[i];
    s->g1[i] = g;
    s->be1[i] = ln1_b[i];
    s->g2v[i] = ln2_w[i];
    s->be2[i] = ln2_b[i];
    s->avec[i] = qkv_w[i] * g;   // row 0 of qkv_w = w_q
    s->bvv[i] = qkv_b[1 + CDIM + i];
    s->bov[i] = out_b[i];
    s->bf2v[i] = ffn2_b[i];
  }
  for (int i = tid; i < FDIM; i += NTHREADS) s->bf1v[i] = ffn1_b[i];
  float aP = 0.f, bP = 0.f;
  for (int i = tid; i < CDIM; i += NTHREADS) {
    aP += qkv_w[i] * ln1_w[i];
    bP += qkv_w[i] * ln1_b[i];
  }
  __syncthreads();
  const float A_ = blockSum(aP, s->scratch);
  const float B0_ = blockSum(bP, s->scratch) + qkv_b[0];

  // ---------- Phase 1: LN stats + q ----------
#pragma unroll 1
  for (int pass = 0; pass < NDIM / NTHREADS; pass++) {
    const int n = pass * NTHREADS + tid;
    const float* xp = x + base + n;
    float s1 = 0.f, s2 = 0.f, sq = 0.f;
#pragma unroll 8
    for (int c = 0; c < CDIM; c++) {
      float v = __ldg(xp + (size_t)c * CS);
      s1 += v;
      s2 = fmaf(v, v, s2);
      sq = fmaf(s->avec[c], v, sq);
    }
    const float mean = s1 * (1.0f / 256.0f);
    const float var = s2 * (1.0f / 256.0f) - mean * mean;
    const float rstd = rsqrtf(var + EPS);
    s->meanA[n] = mean;
    s->rstdA[n] = rstd;
    qA[n] = rstd * (sq - mean * A_) + B0_;
  }
  __syncthreads();

  // ---------- Phase 2: softmax, ybar, ctx ----------
  {
    float mx = -3.4e38f;
#pragma unroll
    for (int k = 0; k < NDIM / NTHREADS; k++)
      mx = fmaxf(mx, qA[k * NTHREADS + tid]);
    mx = blockMax(mx, s->scratch);
    float ev[NDIM / NTHREADS];
    float ssum = 0.f, usum = 0.f;
#pragma unroll
    for (int k = 0; k < NDIM / NTHREADS; k++) {
      const int i = k * NTHREADS + tid;
      float e = expf(qA[i] - mx);
      ev[k] = e;
      ssum += e;
      usum = fmaf(e, s->rstdA[i] * s->meanA[i], usum);
    }
    ssum = blockSum(ssum, s->scratch);
    usum = blockSum(usum, s->scratch);
    const float inv = 1.0f / ssum;
    const float U = usum * inv;
#pragma unroll
    for (int k = 0; k < NDIM / NTHREADS; k++) {
      const int i = k * NTHREADS + tid;
      qA[i] = ev[k] * inv * s->rstdA[i];   // u_n
    }
    __syncthreads();

    const int w = tid >> 5, l = tid & 31;
    for (int r = w; r < CDIM; r += NW) {
      const float* xr = x + base + (size_t)r * CS;
      float acc = 0.f;
#pragma unroll 4
      for (int i = l; i < NDIM; i += 32) acc = fmaf(__ldg(xr + i), qA[i], acc);
      acc = warpSum(acc);
      if (l == 0) s->ybar[r] = s->g1[r] * (acc - U) + s->be1[r];
    }
    __syncthreads();
    for (int r = w; r < CDIM; r += NW) {
      const float* wr = qkv_w + (size_t)(1 + r) * CDIM;
      float acc = 0.f;
#pragma unroll 4
      for (int i = l; i < CDIM; i += 32) acc = fmaf(__ldg(wr + i), s->ybar[i], acc);
      acc = warpSum(acc);
      if (l == 0) s->ctxv[r] = acc + qkv_b[1 + r];
    }
    __syncthreads();
  }

  // ---------- Phase 3: tensor-core tiled pipeline ----------
  const int wid = tid >> 5;
  const int lane = tid & 31;
  const int gid = lane >> 2;
  const int tig = lane & 3;
  const int wrow = (wid & 7) * 32;    // 2 m-frags
  const int cbase = (wid >> 3) * 64;  // 8 n-frags

#pragma unroll 1
  for (int it = 0; it < NTILES; it++) {
    const int n0 = it * TW;

    // build y1 tile
    for (int idx = tid; idx < CDIM * (TW / 4); idx += NTHREADS) {
      const int r = idx >> 5;
      const int j = (idx & 31) << 2;
      float4 xv = *(const float4*)(x + base + (size_t)r * CS + n0 + j);
      float4 mv = *(const float4*)&s->meanA[n0 + j];
      float4 rv = *(const float4*)&s->rstdA[n0 + j];
      const float g = s->g1[r], be = s->be1[r];
      float4 yv;
      yv.x = (xv.x - mv.x) * rv.x * g + be;
      yv.y = (xv.y - mv.y) * rv.y * g + be;
      yv.z = (xv.z - mv.z) * rv.z * g + be;
      yv.w = (xv.w - mv.w) * rv.w * g + be;
      *(float4*)&s->yt[r * YST + j] = yv;
    }
    // first panel barrier inside gemmBig orders yt writes vs reads

    float acc[2][8][4];
#pragma unroll
    for (int mi = 0; mi < 2; mi++)
#pragma unroll
      for (int nf = 0; nf < 8; nf++)
#pragma unroll
        for (int c = 0; c < 4; c++) acc[mi][nf][c] = 0.f;

    // G1: V = W_v @ Y1
    gemmBig(qkv_w + (size_t)(1 + CDIM) * CDIM, CDIM, 0, CDIM, s->yt, acc,
            s->wp, tid, wrow, cbase, gid, tig);
#pragma unroll
    for (int mi = 0; mi < 2; mi++) {
      const int r0 = wrow + mi * 16 + gid;
      const int r1 = r0 + 8;
      const float bv0 = s->bvv[r0], cx0 = s->ctxv[r0];
      const float bv1 = s->bvv[r1], cx1 = s->ctxv[r1];
#pragma unroll
      for (int nf = 0; nf < 8; nf++) {
        const int c = cbase + nf * 8 + 2 * tig;
        float* a = acc[mi][nf];
        *(float2*)&s->yt[r0 * YST + c] =
            make_float2(fmaxf(a[0] + bv0, 0.f) * cx0,
                        fmaxf(a[1] + bv0, 0.f) * cx0);
        *(float2*)&s->yt[r1 * YST + c] =
            make_float2(fmaxf(a[2] + bv1, 0.f) * cx1,
                        fmaxf(a[3] + bv1, 0.f) * cx1);
      }
    }
    __syncthreads();

#pragma unroll
    for (int mi = 0; mi < 2; mi++)
#pragma unroll
      for (int nf = 0; nf < 8; nf++)
#pragma unroll
        for (int c = 0; c < 4; c++) acc[mi][nf][c] = 0.f;

    // G2: O = W_out @ attn ; x2 = x + O + b ; LN2 stats
    gemmBig(out_w, CDIM, 0, CDIM, s->yt, acc, s->wp, tid, wrow, cbase,
            gid, tig);
    {
      float* red1 = s->hbuf;               // [16][YST]
      float* red2 = s->hbuf + 16 * YST;
#pragma unroll
      for (int nf = 0; nf < 8; nf++) {
        const int c = cbase + nf * 8 + 2 * tig;
        float s1a = 0.f, s1b = 0.f, s2a = 0.f, s2b = 0.f;
#pragma unroll
        for (int mi = 0; mi < 2; mi++) {
          const int r0 = wrow + mi * 16 + gid;
          const int r1 = r0 + 8;
          const float bo0 = s->bov[r0], bo1 = s->bov[r1];
          float2 xa = *(const float2*)(x + base + (size_t)r0 * CS + n0 + c);
          float2 xb = *(const float2*)(x + base + (size_t)r1 * CS + n0 + c);
          float* a = acc[mi][nf];
          a[0] += bo0 + xa.x;
          a[1] += bo0 + xa.y;
          a[2] += bo1 + xb.x;
          a[3] += bo1 + xb.y;
          s1a += a[0] + a[2];
          s1b += a[1] + a[3];
          s2a += a[0] * a[0] + a[2] * a[2];
          s2b += a[1] * a[1] + a[3] * a[3];
        }
#pragma unroll
        for (int off = 4; off < 32; off <<= 1) {
          s1a += __shfl_xor_sync(0xffffffffu, s1a, off);
          s1b += __shfl_xor_sync(0xffffffffu, s1b, off);
          s2a += __shfl_xor_sync(0xffffffffu, s2a, off);
          s2b += __shfl_xor_sync(0xffffffffu, s2b, off);
        }
        if (gid == 0) {
          red1[wid * YST + c] = s1a;
          red1[wid * YST + c + 1] = s1b;
          red2[wid * YST + c] = s2a;
          red2[wid * YST + c + 1] = s2b;
        }
      }
      __syncthreads();
      if (tid < TW) {
        // col tid: row-group warps 0..7 hold cols <64, warps 8..15 cols >=64
        const int gb = (tid >= 64) ? 8 : 0;
        float m = 0.f, vv = 0.f;
#pragma unroll
        for (int g = 0; g < 8; g++) {
          m += red1[(gb + g) * YST + tid];
          vv += red2[(gb + g) * YST + tid];
        }
        m *= (1.0f / 256.0f);
        vv = vv * (1.0f / 256.0f) - m * m;
        s->m2s[tid] = m;
        s->r2s[tid] = rsqrtf(vv + EPS);
      }
      __syncthreads();
    }
    // y2 into yt (x2 stays in acc)
#pragma unroll
    for (int mi = 0; mi < 2; mi++) {
      const int r0 = wrow + mi * 16 + gid;
      const int r1 = r0 + 8;
      const float g0 = s->g2v[r0], be0 = s->be2[r0];
      const float g1v = s->g2v[r1], be1v = s->be2[r1];
#pragma unroll
      for (int nf = 0; nf < 8; nf++) {
        const int c = cbase + nf * 8 + 2 * tig;
        const float m0 = s->m2s[c], rr0 = s->r2s[c];
        const float m1 = s->m2s[c + 1], rr1 = s->r2s[c + 1];
        float* a = acc[mi][nf];
        *(float2*)&s->yt[r0 * YST + c] =
            make_float2((a[0] - m0) * rr0 * g0 + be0,
                        (a[1] - m1) * rr1 * g0 + be0);
        *(float2*)&s->yt[r1 * YST + c] =
            make_float2((a[2] - m0) * rr0 * g1v + be1v,
                        (a[3] - m1) * rr1 * g1v + be1v);
      }
    }
    __syncthreads();  // yt(y2) + hbuf(red) settled before FFN

    // FFN: acc(x2) accumulates ffn2; H in 64-row blocks
#pragma unroll 1
    for (int hb = 0; hb < FDIM / 64; hb++) {
      float acc2[4][4];
#pragma unroll
      for (int nf = 0; nf < 4; nf++)
#pragma unroll
        for (int c = 0; c < 4; c++) acc2[nf][c] = 0.f;
      gemmSmall(ffn1_w + (size_t)hb * 64 * CDIM, s->yt, acc2, s->wp,
                tid, wid, gid, tig);
      {
        const int mr = (wid & 3) * 16;
        const int cb2 = (wid >> 2) * 32;
        const int r0 = mr + gid;
        const int r1 = r0 + 8;
        const float bf0 = s->bf1v[hb * 64 + r0];
        const float bf1 = s->bf1v[hb * 64 + r1];
#pragma unroll
        for (int nf = 0; nf < 4; nf++) {
          const int c = cb2 + nf * 8 + 2 * tig;
          float* a = acc2[nf];
          float h0 = a[0] + bf0, h1 = a[1] + bf0;
          float h2 = a[2] + bf1, h3 = a[3] + bf1;
          h0 = (h0 > 0.f) ? h0 : 0.1f * h0;
          h1 = (h1 > 0.f) ? h1 : 0.1f * h1;
          h2 = (h2 > 0.f) ? h2 : 0.1f * h2;
          h3 = (h3 > 0.f) ? h3 : 0.1f * h3;
          *(float2*)&s->hbuf[r0 * YST + c] = make_float2(h0, h1);
          *(float2*)&s->hbuf[r1 * YST + c] = make_float2(h2, h3);
        }
      }
      __syncthreads();  // hbuf ready before G4 reads
      // G4 partial: acc += W2[:, hb*64..+64) @ Hblk
      gemmBig(ffn2_w, FDIM, hb * 64, 64, s->hbuf, acc, s->wp,
              tid, wrow, cbase, gid, tig);
    }

    // final: out = x2 + ffn2(H) + b2 (in acc)
#pragma unroll
    for (int mi = 0; mi < 2; mi++) {
      const int r0 = wrow + mi * 16 + gid;
      const int r1 = r0 + 8;
      const float bf0 = s->bf2v[r0], bf1 = s->bf2v[r1];
#pragma unroll
      for (int nf = 0; nf < 8; nf++) {
        const int c = cbase + nf * 8 + 2 * tig;
        float* a = acc[mi][nf];
        float* op0 = out + base + (size_t)r0 * CS + n0 + c;
        float* op1 = out + base + (size_t)r1 * CS + n0 + c;
        *(float2*)op0 = make_float2(a[0] + bf0, a[1] + bf0);
        *(float2*)op1 = make_float2(a[2] + bf1, a[3] + bf1);
      }
    }
    __syncthreads();  // protect yt/hbuf reuse next tile
  }
}

}  // namespace

extern "C" void kernel_launch(void* const* d_in, const int* in_sizes, int n_in,
                              void* d_out, int out_size) {
  const float* x      = (const float*)d_in[0];
  const float* ln1_w  = (const float*)d_in[1];
  const float* ln1_b  = (const float*)d_in[2];
  const float* qkv_w  = (const float*)d_in[3];
  const float* qkv_b  = (const float*)d_in[4];
  const float* out_w  = (const float*)d_in[5];
  const float* out_b  = (const float*)d_in[6];
  const float* ln2_w  = (const float*)d_in[7];
  const float* ln2_b  = (const float*)d_in[8];
  const float* ffn1_w = (const float*)d_in[9];
  const float* ffn1_b = (const float*)d_in[10];
  const float* ffn2_w = (const float*)d_in[11];
  const float* ffn2_b = (const float*)d_in[12];
  float* out = (float*)d_out;

  const int B = in_sizes[0] / (CDIM * 4 * NDIM);
  const int grid = B * 4;
  const int smem = (int)sizeof(Smem);
  cudaFuncSetAttribute(fused_block_kernel,
                       cudaFuncAttributeMaxDynamicSharedMemorySize, smem);
  fused_block_kernel<<<grid, NTHREADS, smem>>>(
      x, ln1_w, ln1_b, qkv_w, qkv_b, out_w, out_b, ln2_w, ln2_b,
      ffn1_w, ffn1_b, ffn2_w, ffn2_b, out);
}

// round 17
// speedup vs baseline: 1.4097x; 1.4097x over previous
#include <cuda_runtime.h>
#include <cstdint>

namespace {

constexpr int CDIM = 256;
constexpr int FDIM = 512;
constexpr int NDIM = 1024;
constexpr int TW = 128;            // tile width (positions)
constexpr int NTILES = NDIM / TW;  // 8
constexpr int NTHREADS = 256;
constexpr int NW = 8;
constexpr int CS = 4 * NDIM;       // channel stride in x (floats)
constexpr int YST = 136;           // yt/hbuf row stride
constexpr int WST = 264;           // big panel row stride [k][256]
constexpr int WSTS = 72;           // small panel row stride [k][64]
constexpr int PLANE = 8 * WST;     // one k-panel plane (2112 floats)
constexpr int PBUF = 2 * PLANE;    // hi + lo
constexpr int MAXSLAB = 128;       // B=32 * 4 planes
constexpr float EPS = 1e-5f;
constexpr unsigned TMASK = 0xFFFFE000u;  // tf32 truncation mask

// Cross-kernel scratch (static device arrays — allocation-free).
__device__ float g_meanS[MAXSLAB * NDIM];
__device__ float g_rstdS[MAXSLAB * NDIM];
__device__ float g_ctxS[MAXSLAB * CDIM];

struct SmemP {
  float meanA[NDIM];
  float rstdA[NDIM];
  float qA[NDIM];
  float g1[CDIM], be1[CDIM], avec[CDIM], ybar[CDIM];
  float scratch[40];
};

struct SmemT {
  float yt[CDIM * YST];     // y1/attn/y2 tile
  float hbuf[64 * YST];     // FFN H block; aliases LN2 red
  float wp[2 * PBUF];       // dbuf x (hi,lo) weight panels
  float meanT[TW], rstdT[TW];
  float g1[CDIM], be1[CDIM], g2v[CDIM], be2[CDIM];
  float ctxv[CDIM], bvv[CDIM], bov[CDIM], bf2v[CDIM];
  float bf1v[FDIM];
  float m2s[TW], r2s[TW];
};

__device__ __forceinline__ void mma8(float* d, const unsigned* a,
                                     unsigned b0, unsigned b1) {
  asm volatile(
      "mma.sync.aligned.m16n8k8.row.col.f32.tf32.tf32.f32 "
      "{%0,%1,%2,%3}, {%4,%5,%6,%7}, {%8,%9}, {%0,%1,%2,%3};\n"
      : "+f"(d[0]), "+f"(d[1]), "+f"(d[2]), "+f"(d[3])
      : "r"(a[0]), "r"(a[1]), "r"(a[2]), "r"(a[3]), "r"(b0), "r"(b1));
}

__device__ __forceinline__ float warpSum(float v) {
#pragma unroll
  for (int o = 16; o; o >>= 1) v += __shfl_xor_sync(0xffffffffu, v, o);
  return v;
}

__device__ __forceinline__ float blockSum(float v, float* scr) {
  v = warpSum(v);
  const int w = threadIdx.x >> 5;
  if ((threadIdx.x & 31) == 0) scr[w] = v;
  __syncthreads();
  if (threadIdx.x == 0) {
    float t = 0.f;
#pragma unroll
    for (int i = 0; i < NW; i++) t += scr[i];
    scr[8] = t;
  }
  __syncthreads();
  float r = scr[8];
  __syncthreads();
  return r;
}

__device__ __forceinline__ float blockMax(float v, float* scr) {
#pragma unroll
  for (int o = 16; o; o >>= 1) v = fmaxf(v, __shfl_xor_sync(0xffffffffu, v, o));
  const int w = threadIdx.x >> 5;
  if ((threadIdx.x & 31) == 0) scr[w] = v;
  __syncthreads();
  if (threadIdx.x == 0) {
    float t = scr[0];
#pragma unroll
    for (int i = 1; i < NW; i++) t = fmaxf(t, scr[i]);
    scr[8] = t;
  }
  __syncthreads();
  float r = scr[8];
  __syncthreads();
  return r;
}

// ============================ Kernel P: per-slab prep =======================
__global__ void __launch_bounds__(NTHREADS, 1)
prep_kernel(const float* __restrict__ x,
            const float* __restrict__ ln1_w, const float* __restrict__ ln1_b,
            const float* __restrict__ qkv_w, const float* __restrict__ qkv_b) {
  extern __shared__ __align__(16) char smem_raw[];
  SmemP* s = reinterpret_cast<SmemP*>(smem_raw);
  const int tid = threadIdx.x;
  const int slab = blockIdx.x;
  const int b = slab >> 2;
  const int p = slab & 3;
  const size_t base = (size_t)b * (CDIM * 4 * NDIM) + (size_t)p * NDIM;

  for (int i = tid; i < CDIM; i += NTHREADS) {
    float g = ln1_w[i];
    s->g1[i] = g;
    s->be1[i] = ln1_b[i];
    s->avec[i] = qkv_w[i] * g;  // row 0 of qkv_w = w_q
  }
  float aP = 0.f, bP = 0.f;
  for (int i = tid; i < CDIM; i += NTHREADS) {
    aP += qkv_w[i] * ln1_w[i];
    bP += qkv_w[i] * ln1_b[i];
  }
  __syncthreads();
  const float A_ = blockSum(aP, s->scratch);
  const float B0_ = blockSum(bP, s->scratch) + qkv_b[0];

  // LN stats + q per column
#pragma unroll 1
  for (int pass = 0; pass < NDIM / NTHREADS; pass++) {
    const int n = pass * NTHREADS + tid;
    const float* xp = x + base + n;
    float s1 = 0.f, s2 = 0.f, sq = 0.f;
#pragma unroll 8
    for (int c = 0; c < CDIM; c++) {
      float v = __ldg(xp + (size_t)c * CS);
      s1 += v;
      s2 = fmaf(v, v, s2);
      sq = fmaf(s->avec[c], v, sq);
    }
    const float mean = s1 * (1.0f / 256.0f);
    const float var = s2 * (1.0f / 256.0f) - mean * mean;
    const float rstd = rsqrtf(var + EPS);
    s->meanA[n] = mean;
    s->rstdA[n] = rstd;
    s->qA[n] = rstd * (sq - mean * A_) + B0_;
  }
  __syncthreads();

  // softmax over n, ybar, ctx
  float mx = -3.4e38f;
#pragma unroll
  for (int k = 0; k < 4; k++) mx = fmaxf(mx, s->qA[k * NTHREADS + tid]);
  mx = blockMax(mx, s->scratch);
  float ev[4];
  float ssum = 0.f, usum = 0.f;
#pragma unroll
  for (int k = 0; k < 4; k++) {
    const int i = k * NTHREADS + tid;
    float e = expf(s->qA[i] - mx);
    ev[k] = e;
    ssum += e;
    usum = fmaf(e, s->rstdA[i] * s->meanA[i], usum);
  }
  ssum = blockSum(ssum, s->scratch);
  usum = blockSum(usum, s->scratch);
  const float inv = 1.0f / ssum;
  const float U = usum * inv;
#pragma unroll
  for (int k = 0; k < 4; k++) {
    const int i = k * NTHREADS + tid;
    s->qA[i] = ev[k] * inv * s->rstdA[i];  // u_n
  }
  __syncthreads();

  const int w = tid >> 5, l = tid & 31;
  for (int r = w; r < CDIM; r += NW) {
    const float* xr = x + base + (size_t)r * CS;
    float acc = 0.f;
#pragma unroll 4
    for (int i = l; i < NDIM; i += 32) acc = fmaf(__ldg(xr + i), s->qA[i], acc);
    acc = warpSum(acc);
    if (l == 0) s->ybar[r] = s->g1[r] * (acc - U) + s->be1[r];
  }
  __syncthreads();
  for (int r = w; r < CDIM; r += NW) {
    const float* wr = qkv_w + (size_t)(1 + r) * CDIM;
    float acc = 0.f;
#pragma unroll 4
    for (int i = l; i < CDIM; i += 32) acc = fmaf(__ldg(wr + i), s->ybar[i], acc);
    acc = warpSum(acc);
    if (l == 0) g_ctxS[slab * CDIM + r] = acc + qkv_b[1 + r];
  }

  // persist stats
  for (int i = tid; i < NDIM; i += NTHREADS) {
    g_meanS[slab * NDIM + i] = s->meanA[i];
    g_rstdS[slab * NDIM + i] = s->rstdA[i];
  }
}

// ====================== tile kernel GEMM helpers (r13) ======================
__device__ __forceinline__ void storeSplit8(float* wh, float* wl, int lrow,
                                            const float4& f0, const float4& f1) {
  float v[8] = {f0.x, f0.y, f0.z, f0.w, f1.x, f1.y, f1.z, f1.w};
#pragma unroll
  for (int i = 0; i < 8; i++) {
    unsigned h = __float_as_uint(v[i]) & TMASK;
    wh[i * WST + lrow] = __uint_as_float(h);
    float lo = v[i] - __uint_as_float(h);
    wl[i * WST + lrow] = __uint_as_float(__float_as_uint(lo) & TMASK);
  }
}

// acc[256 x TW] += W[256 x kdim] @ Ys ; 8 warps, warp w: rows w*32 (2 m-frags)
// x 128 cols (16 n-frags). TF32 3-pass split. PD=8 double-buffered panels.
__device__ __forceinline__ void gemmBig(const float* __restrict__ Wg, int ldw,
                                        int kcol0, int kdim,
                                        const float* __restrict__ Ys,
                                        float (&acc)[2][16][4], float* wp,
                                        int tid, int wid, int gid, int tig) {
  const int wrow = wid * 32;
  const float* gp = Wg + (size_t)tid * ldw + kcol0;
  float4 f0 = *(const float4*)gp;
  float4 f1 = *(const float4*)(gp + 4);
  storeSplit8(wp, wp + PLANE, tid, f0, f1);
  __syncthreads();
  const int P = kdim / 8;
#pragma unroll 1
  for (int p = 0; p < P; p++) {
    if (p + 1 < P) {
      f0 = *(const float4*)(gp + (p + 1) * 8);
      f1 = *(const float4*)(gp + (p + 1) * 8 + 4);
    }
    const float* wh = wp + (p & 1) * PBUF;
    const float* wl = wh + PLANE;
    unsigned ah[2][4], al[2][4];
#pragma unroll
    for (int mi = 0; mi < 2; mi++) {
      const int rb = wrow + mi * 16 + gid;
      ah[mi][0] = __float_as_uint(wh[tig * WST + rb]);
      ah[mi][1] = __float_as_uint(wh[tig * WST + rb + 8]);
      ah[mi][2] = __float_as_uint(wh[(tig + 4) * WST + rb]);
      ah[mi][3] = __float_as_uint(wh[(tig + 4) * WST + rb + 8]);
      al[mi][0] = __float_as_uint(wl[tig * WST + rb]);
      al[mi][1] = __float_as_uint(wl[tig * WST + rb + 8]);
      al[mi][2] = __float_as_uint(wl[(tig + 4) * WST + rb]);
      al[mi][3] = __float_as_uint(wl[(tig + 4) * WST + rb + 8]);
    }
    const float* yb = Ys + p * 8 * YST;
#pragma unroll
    for (int nf = 0; nf < 16; nf++) {
      const int cb = nf * 8 + gid;
      float y0 = yb[tig * YST + cb];
      float y1 = yb[(tig + 4) * YST + cb];
      unsigned bh0 = __float_as_uint(y0) & TMASK;
      unsigned bh1 = __float_as_uint(y1) & TMASK;
      unsigned bl0 = __float_as_uint(y0 - __uint_as_float(bh0)) & TMASK;
      unsigned bl1 = __float_as_uint(y1 - __uint_as_float(bh1)) & TMASK;
      mma8(acc[0][nf], ah[0], bh0, bh1);
      mma8(acc[0][nf], ah[0], bl0, bl1);
      mma8(acc[0][nf], al[0], bh0, bh1);
      mma8(acc[1][nf], ah[1], bh0, bh1);
      mma8(acc[1][nf], ah[1], bl0, bl1);
      mma8(acc[1][nf], al[1], bh0, bh1);
    }
    if (p + 1 < P) {
      float* wh2 = wp + ((p + 1) & 1) * PBUF;
      storeSplit8(wh2, wh2 + PLANE, tid, f0, f1);
    }
    __syncthreads();
  }
}

// acc2[64 x TW] += W[64 x 256] @ Ys ; warp w: m-frag (w&3)*16, cols (w>>2)*64.
__device__ __forceinline__ void gemmSmall(const float* __restrict__ Wg,
                                          const float* __restrict__ Ys,
                                          float (&acc2)[8][4], float* wp,
                                          int tid, int wid, int gid, int tig) {
  const int mr = (wid & 3) * 16;
  const int cbase = (wid >> 2) * 64;
  const int lrow = tid & 63;
  const int ks = (tid >> 6) * 4;
  const float* gp = Wg + (size_t)lrow * CDIM + ks;
  float4 f = *(const float4*)gp;
  {
    float* wh = wp;
    float* wl = wp + PLANE;
#pragma unroll
    for (int i = 0; i < 4; i++) {
      float v = (&f.x)[i];
      unsigned h = __float_as_uint(v) & TMASK;
      wh[(ks + i) * WSTS + lrow] = __uint_as_float(h);
      float lo = v - __uint_as_float(h);
      wl[(ks + i) * WSTS + lrow] = __uint_as_float(__float_as_uint(lo) & TMASK);
    }
  }
  __syncthreads();
  const int P = CDIM / 16;
#pragma unroll 1
  for (int p = 0; p < P; p++) {
    if (p + 1 < P) f = *(const float4*)(gp + (p + 1) * 16);
    const float* wh = wp + (p & 1) * PBUF;
    const float* wl = wh + PLANE;
#pragma unroll
    for (int kc = 0; kc < 16; kc += 8) {
      unsigned ah[4], al[4];
      const int rb = mr + gid;
      ah[0] = __float_as_uint(wh[(kc + tig) * WSTS + rb]);
      ah[1] = __float_as_uint(wh[(kc + tig) * WSTS + rb + 8]);
      ah[2] = __float_as_uint(wh[(kc + tig + 4) * WSTS + rb]);
      ah[3] = __float_as_uint(wh[(kc + tig + 4) * WSTS + rb + 8]);
      al[0] = __float_as_uint(wl[(kc + tig) * WSTS + rb]);
      al[1] = __float_as_uint(wl[(kc + tig) * WSTS + rb + 8]);
      al[2] = __float_as_uint(wl[(kc + tig + 4) * WSTS + rb]);
      al[3] = __float_as_uint(wl[(kc + tig + 4) * WSTS + rb + 8]);
      const float* yb = Ys + (p * 16 + kc) * YST;
#pragma unroll
      for (int nf = 0; nf < 8; nf++) {
        const int cb = cbase + nf * 8 + gid;
        float y0 = yb[tig * YST + cb];
        float y1 = yb[(tig + 4) * YST + cb];
        unsigned bh0 = __float_as_uint(y0) & TMASK;
        unsigned bh1 = __float_as_uint(y1) & TMASK;
        unsigned bl0 = __float_as_uint(y0 - __uint_as_float(bh0)) & TMASK;
        unsigned bl1 = __float_as_uint(y1 - __uint_as_float(bh1)) & TMASK;
        mma8(acc2[nf], ah, bh0, bh1);
        mma8(acc2[nf], ah, bl0, bl1);
        mma8(acc2[nf], al, bh0, bh1);
      }
    }
    if (p + 1 < P) {
      float* wh2 = wp + ((p + 1) & 1) * PBUF;
      float* wl2 = wh2 + PLANE;
#pragma unroll
      for (int i = 0; i < 4; i++) {
        float v = (&f.x)[i];
        unsigned h = __float_as_uint(v) & TMASK;
        wh2[(ks + i) * WSTS + lrow] = __uint_as_float(h);
        float lo = v - __uint_as_float(h);
        wl2[(ks + i) * WSTS + lrow] = __uint_as_float(__float_as_uint(lo) & TMASK);
      }
    }
    __syncthreads();
  }
}

// ======================== Kernel T: one tile per CTA ========================
__global__ void __launch_bounds__(NTHREADS, 1)
tile_kernel(const float* __restrict__ x,
            const float* __restrict__ ln1_w, const float* __restrict__ ln1_b,
            const float* __restrict__ qkv_w, const float* __restrict__ qkv_b,
            const float* __restrict__ out_w, const float* __restrict__ out_b,
            const float* __restrict__ ln2_w, const float* __restrict__ ln2_b,
            const float* __restrict__ ffn1_w, const float* __restrict__ ffn1_b,
            const float* __restrict__ ffn2_w, const float* __restrict__ ffn2_b,
            float* __restrict__ out) {
  extern __shared__ __align__(16) char smem_raw[];
  SmemT* s = reinterpret_cast<SmemT*>(smem_raw);
  const int tid = threadIdx.x;
  const int slab = blockIdx.x >> 3;  // NTILES = 8
  const int it = blockIdx.x & 7;
  const int b = slab >> 2;
  const int p = slab & 3;
  const size_t base = (size_t)b * (CDIM * 4 * NDIM) + (size_t)p * NDIM;
  const int n0 = it * TW;

  // prologue: vectors + stat slices
  for (int i = tid; i < CDIM; i += NTHREADS) {
    s->g1[i] = ln1_w[i];
    s->be1[i] = ln1_b[i];
    s->g2v[i] = ln2_w[i];
    s->be2[i] = ln2_b[i];
    s->ctxv[i] = g_ctxS[slab * CDIM + i];
    s->bvv[i] = qkv_b[1 + CDIM + i];
    s->bov[i] = out_b[i];
    s->bf2v[i] = ffn2_b[i];
  }
  for (int i = tid; i < FDIM; i += NTHREADS) s->bf1v[i] = ffn1_b[i];
  if (tid < TW) {
    s->meanT[tid] = g_meanS[slab * NDIM + n0 + tid];
    s->rstdT[tid] = g_rstdS[slab * NDIM + n0 + tid];
  }
  __syncthreads();

  const int wid = tid >> 5;
  const int lane = tid & 31;
  const int gid = lane >> 2;
  const int tig = lane & 3;
  const int wrow = wid * 32;

  // build y1 tile
  for (int idx = tid; idx < CDIM * (TW / 4); idx += NTHREADS) {
    const int r = idx >> 5;
    const int j = (idx & 31) << 2;
    float4 xv = *(const float4*)(x + base + (size_t)r * CS + n0 + j);
    float4 mv = *(const float4*)&s->meanT[j];
    float4 rv = *(const float4*)&s->rstdT[j];
    const float g = s->g1[r], be = s->be1[r];
    float4 yv;
    yv.x = (xv.x - mv.x) * rv.x * g + be;
    yv.y = (xv.y - mv.y) * rv.y * g + be;
    yv.z = (xv.z - mv.z) * rv.z * g + be;
    yv.w = (xv.w - mv.w) * rv.w * g + be;
    *(float4*)&s->yt[r * YST + j] = yv;
  }
  // first panel barrier inside gemmBig orders yt writes vs reads

  float acc[2][16][4];
#pragma unroll
  for (int mi = 0; mi < 2; mi++)
#pragma unroll
    for (int nf = 0; nf < 16; nf++)
#pragma unroll
      for (int c = 0; c < 4; c++) acc[mi][nf][c] = 0.f;

  // G1: V = W_v @ Y1
  gemmBig(qkv_w + (size_t)(1 + CDIM) * CDIM, CDIM, 0, CDIM, s->yt, acc,
          s->wp, tid, wid, gid, tig);
#pragma unroll
  for (int mi = 0; mi < 2; mi++) {
    const int r0 = wrow + mi * 16 + gid;
    const int r1 = r0 + 8;
    const float bv0 = s->bvv[r0], cx0 = s->ctxv[r0];
    const float bv1 = s->bvv[r1], cx1 = s->ctxv[r1];
#pragma unroll
    for (int nf = 0; nf < 16; nf++) {
      const int c = nf * 8 + 2 * tig;
      float* a = acc[mi][nf];
      *(float2*)&s->yt[r0 * YST + c] =
          make_float2(fmaxf(a[0] + bv0, 0.f) * cx0,
                      fmaxf(a[1] + bv0, 0.f) * cx0);
      *(float2*)&s->yt[r1 * YST + c] =
          make_float2(fmaxf(a[2] + bv1, 0.f) * cx1,
                      fmaxf(a[3] + bv1, 0.f) * cx1);
    }
  }
  __syncthreads();

#pragma unroll
  for (int mi = 0; mi < 2; mi++)
#pragma unroll
    for (int nf = 0; nf < 16; nf++)
#pragma unroll
      for (int c = 0; c < 4; c++) acc[mi][nf][c] = 0.f;

  // G2: O = W_out @ attn ; x2 = x + O + b ; LN2 stats
  gemmBig(out_w, CDIM, 0, CDIM, s->yt, acc, s->wp, tid, wid, gid, tig);
  {
    float* red1 = s->hbuf;  // [8][YST]
    float* red2 = s->hbuf + 8 * YST;
#pragma unroll
    for (int nf = 0; nf < 16; nf++) {
      const int c = nf * 8 + 2 * tig;
      float s1a = 0.f, s1b = 0.f, s2a = 0.f, s2b = 0.f;
#pragma unroll
      for (int mi = 0; mi < 2; mi++) {
        const int r0 = wrow + mi * 16 + gid;
        const int r1 = r0 + 8;
        const float bo0 = s->bov[r0], bo1 = s->bov[r1];
        float2 xa = *(const float2*)(x + base + (size_t)r0 * CS + n0 + c);
        float2 xb = *(const float2*)(x + base + (size_t)r1 * CS + n0 + c);
        float* a = acc[mi][nf];
        a[0] += bo0 + xa.x;
        a[1] += bo0 + xa.y;
        a[2] += bo1 + xb.x;
        a[3] += bo1 + xb.y;
        s1a += a[0] + a[2];
        s1b += a[1] + a[3];
        s2a += a[0] * a[0] + a[2] * a[2];
        s2b += a[1] * a[1] + a[3] * a[3];
      }
#pragma unroll
      for (int off = 4; off < 32; off <<= 1) {
        s1a += __shfl_xor_sync(0xffffffffu, s1a, off);
        s1b += __shfl_xor_sync(0xffffffffu, s1b, off);
        s2a += __shfl_xor_sync(0xffffffffu, s2a, off);
        s2b += __shfl_xor_sync(0xffffffffu, s2b, off);
      }
      if (gid == 0) {
        red1[wid * YST + c] = s1a;
        red1[wid * YST + c + 1] = s1b;
        red2[wid * YST + c] = s2a;
        red2[wid * YST + c + 1] = s2b;
      }
    }
    __syncthreads();
    if (tid < TW) {
      float m = 0.f, vv = 0.f;
#pragma unroll
      for (int g = 0; g < 8; g++) {
        m += red1[g * YST + tid];
        vv += red2[g * YST + tid];
      }
      m *= (1.0f / 256.0f);
      vv = vv * (1.0f / 256.0f) - m * m;
      s->m2s[tid] = m;
      s->r2s[tid] = rsqrtf(vv + EPS);
    }
    __syncthreads();
  }
  // y2 into yt (x2 stays in acc)
#pragma unroll
  for (int mi = 0; mi < 2; mi++) {
    const int r0 = wrow + mi * 16 + gid;
    const int r1 = r0 + 8;
    const float g0 = s->g2v[r0], be0 = s->be2[r0];
    const float g1v = s->g2v[r1], be1v = s->be2[r1];
#pragma unroll
    for (int nf = 0; nf < 16; nf++) {
      const int c = nf * 8 + 2 * tig;
      const float m0 = s->m2s[c], rr0 = s->r2s[c];
      const float m1 = s->m2s[c + 1], rr1 = s->r2s[c + 1];
      float* a = acc[mi][nf];
      *(float2*)&s->yt[r0 * YST + c] =
          make_float2((a[0] - m0) * rr0 * g0 + be0,
                      (a[1] - m1) * rr1 * g0 + be0);
      *(float2*)&s->yt[r1 * YST + c] =
          make_float2((a[2] - m0) * rr0 * g1v + be1v,
                      (a[3] - m1) * rr1 * g1v + be1v);
    }
  }
  __syncthreads();  // yt(y2) + hbuf(red) settled before FFN

  // FFN: acc(x2) accumulates ffn2; H in 64-row blocks
#pragma unroll 1
  for (int hb = 0; hb < FDIM / 64; hb++) {
    float acc2[8][4];
#pragma unroll
    for (int nf = 0; nf < 8; nf++)
#pragma unroll
      for (int c = 0; c < 4; c++) acc2[nf][c] = 0.f;
    gemmSmall(ffn1_w + (size_t)hb * 64 * CDIM, s->yt, acc2, s->wp,
              tid, wid, gid, tig);
    {
      const int mr = (wid & 3) * 16;
      const int cbase = (wid >> 2) * 64;
      const int r0 = mr + gid;
      const int r1 = r0 + 8;
      const float bf0 = s->bf1v[hb * 64 + r0];
      const float bf1 = s->bf1v[hb * 64 + r1];
#pragma unroll
      for (int nf = 0; nf < 8; nf++) {
        const int c = cbase + nf * 8 + 2 * tig;
        float* a = acc2[nf];
        float h0 = a[0] + bf0, h1 = a[1] + bf0;
        float h2 = a[2] + bf1, h3 = a[3] + bf1;
        h0 = (h0 > 0.f) ? h0 : 0.1f * h0;
        h1 = (h1 > 0.f) ? h1 : 0.1f * h1;
        h2 = (h2 > 0.f) ? h2 : 0.1f * h2;
        h3 = (h3 > 0.f) ? h3 : 0.1f * h3;
        *(float2*)&s->hbuf[r0 * YST + c] = make_float2(h0, h1);
        *(float2*)&s->hbuf[r1 * YST + c] = make_float2(h2, h3);
      }
    }
    __syncthreads();  // hbuf ready before G4 reads
    // G4 partial: acc += W2[:, hb*64..+64) @ Hblk
    gemmBig(ffn2_w, FDIM, hb * 64, 64, s->hbuf, acc, s->wp,
            tid, wid, gid, tig);
  }

  // final: out = x2 + ffn2(H) + b2 (in acc)
#pragma unroll
  for (int mi = 0; mi < 2; mi++) {
    const int r0 = wrow + mi * 16 + gid;
    const int r1 = r0 + 8;
    const float bf0 = s->bf2v[r0], bf1 = s->bf2v[r1];
#pragma unroll
    for (int nf = 0; nf < 16; nf++) {
      const int c = nf * 8 + 2 * tig;
      float* a = acc[mi][nf];
      float* op0 = out + base + (size_t)r0 * CS + n0 + c;
      float* op1 = out + base + (size_t)r1 * CS + n0 + c;
      *(float2*)op0 = make_float2(a[0] + bf0, a[1] + bf0);
      *(float2*)op1 = make_float2(a[2] + bf1, a[3] + bf1);
    }
  }
}

}  // namespace

extern "C" void kernel_launch(void* const* d_in, const int* in_sizes, int n_in,
                              void* d_out, int out_size) {
  const float* x      = (const float*)d_in[0];
  const float* ln1_w  = (const float*)d_in[1];
  const float* ln1_b  = (const float*)d_in[2];
  const float* qkv_w  = (const float*)d_in[3];
  const float* qkv_b  = (const float*)d_in[4];
  const float* out_w  = (const float*)d_in[5];
  const float* out_b  = (const float*)d_in[6];
  const float* ln2_w  = (const float*)d_in[7];
  const float* ln2_b  = (const float*)d_in[8];
  const float* ffn1_w = (const float*)d_in[9];
  const float* ffn1_b = (const float*)d_in[10];
  const float* ffn2_w = (const float*)d_in[11];
  const float* ffn2_b = (const float*)d_in[12];
  float* out = (float*)d_out;

  const int B = in_sizes[0] / (CDIM * 4 * NDIM);
  const int slabs = B * 4;
  const int smemP = (int)sizeof(SmemP);
  const int smemT = (int)sizeof(SmemT);
  cudaFuncSetAttribute(prep_kernel,
                       cudaFuncAttributeMaxDynamicSharedMemorySize, smemP);
  cudaFuncSetAttribute(tile_kernel,
                       cudaFuncAttributeMaxDynamicSharedMemorySize, smemT);
  prep_kernel<<<slabs, NTHREADS, smemP>>>(x, ln1_w, ln1_b, qkv_w, qkv_b);
  tile_kernel<<<slabs * NTILES, NTHREADS, smemT>>>(
      x, ln1_w, ln1_b, qkv_w, qkv_b, out_w, out_b, ln2_w, ln2_b,
      ffn1_w, ffn1_b, ffn2_w, ffn2_b, out);
}